// round 14
// baseline (speedup 1.0000x reference)
#include <cuda_runtime.h>
#include <cuda_fp16.h>
#include <math.h>

#define H 128
#define CDIM 40
#define TMPW 64   /* padded half-row stride for layer-3 gather (128B) */
#define MAXN 100000
#define KP 40     /* padded k-stride (halves) for 32-k W smem tiles */
#define KPA 136   /* padded k-stride (halves) for full-K A tiles (LDSM conflict-free) */
#define KP2 136   /* padded k-stride (halves) for full-K W2 tile */
#define SMEM_FUSED ((2 * 128 * KPA + 2 * 128 * KP) * 2)  /* 90112 B */

// scratch (device globals: allocation-free rule)
__device__ __align__(16) __half g_xh [(size_t)MAXN * H];     // 25.6 MB (x fp16; layer-2 out)
__device__ __align__(16) __half g_hb [(size_t)MAXN * H];     // 25.6 MB (layer-1 out)
__device__ __align__(16) __half g_tmp[(size_t)MAXN * TMPW];  // 12.8 MB
__device__ int g_rowptr[MAXN + 1];
// pre-split, pre-transposed weights: WT[n][k] fp16 hi/lo halves of f32
__device__ __align__(16) __half g_W0T_hi[H * H], g_W0T_lo[H * H];
__device__ __align__(16) __half g_W1T_hi[H * H], g_W1T_lo[H * H];
__device__ __align__(16) __half g_W2T_hi[CDIM * H], g_W2T_lo[CDIM * H];

__device__ __forceinline__ unsigned s2u(const void* p) {
    return (unsigned)__cvta_generic_to_shared(p);
}

#define LDSM_X4(r0, r1, r2, r3, addr)                                        \
    asm volatile("ldmatrix.sync.aligned.m8n8.x4.shared.b16 {%0,%1,%2,%3}, [%4];" \
                 : "=r"(r0), "=r"(r1), "=r"(r2), "=r"(r3) : "r"(addr))

#define MMA(cacc, a, b0, b1)                                                 \
    asm volatile("mma.sync.aligned.m16n8k16.row.col.f32.f16.f16.f32 "        \
                 "{%0,%1,%2,%3}, {%4,%5,%6,%7}, {%8,%9}, {%0,%1,%2,%3};"     \
                 : "+f"(cacc[0]), "+f"(cacc[1]), "+f"(cacc[2]), "+f"(cacc[3])\
                 : "r"(a[0]), "r"(a[1]), "r"(a[2]), "r"(a[3]), "r"(b0), "r"(b1))

// ---------------- fused prep: f2h + rowptr + 3x weight split -----------------
__global__ void prep_kernel(const float* __restrict__ x, int n2h, int bF,
                            const int* __restrict__ dst, int E, int N, int bR,
                            const float* __restrict__ W0, const float* __restrict__ W1,
                            const float* __restrict__ W2, int bW,
                            __half* __restrict__ xh, int* __restrict__ rp) {
    const int b = blockIdx.x, t = threadIdx.x;
    if (b < bF) {                                  // f32 -> f16 convert of x
        int i = b * 256 + t;
        if (i < n2h) {
            float2 v = ((const float2*)x)[i];
            ((__half2*)xh)[i] = __floats2half2_rn(v.x, v.y);
        }
    } else if (b < bF + bR) {                      // row_ptr via lower_bound
        int i = (b - bF) * 256 + t;
        if (i <= N) {
            int lo = 0, hi = E;
            while (lo < hi) {
                int m = (lo + hi) >> 1;
                if (dst[m] < i) lo = m + 1; else hi = m;
            }
            rp[i] = lo;
        }
    } else if (b < bF + bR + 2 * bW) {             // W0 / W1 split+transpose
        int wi = b - bF - bR;
        const float* W = (wi < bW) ? W0 : W1;
        __half* Th = (wi < bW) ? g_W0T_hi : g_W1T_hi;
        __half* Tl = (wi < bW) ? g_W0T_lo : g_W1T_lo;
        int i = (wi % bW) * 256 + t;
        if (i < H * H) {
            int k = i >> 7, n = i & 127;
            float v = W[k * H + n];
            __half hi = __float2half_rn(v);
            Th[n * H + k] = hi;
            Tl[n * H + k] = __float2half_rn(v - __half2float(hi));
        }
    } else {                                       // W2 split+transpose [k<128][n<40]
        int i = (b - bF - bR - 2 * bW) * 256 + t;
        if (i < H * CDIM) {
            int k = i / CDIM, n = i % CDIM;
            float v = W2[k * CDIM + n];
            __half hi = __float2half_rn(v);
            g_W2T_hi[n * H + k] = hi;
            g_W2T_lo[n * H + k] = __float2half_rn(v - __half2float(hi));
        }
    }
}

// ============== FUSED: SPMM (rows) -> split-fp16 MMA -> tanh -> C =============
// Block = 128 output rows. Phase 1: warp wid computes rows wid*16..+15 via the
// proven gather loop, splitting f32 accs directly into full-K sAh/sAl tiles.
// Phase 2: proven LDSM+MMA loop; A from resident smem tile, W staged per 32-k.
__global__ __launch_bounds__(256, 2) void fused_layer(const __half* __restrict__ hin,
                                                      const int* __restrict__ src,
                                                      const float* __restrict__ ew,
                                                      const int* __restrict__ rp,
                                                      const __half* __restrict__ WThi,
                                                      const __half* __restrict__ WTlo,
                                                      __half* __restrict__ C, int N) {
    extern __shared__ __align__(16) __half dsm[];
    __half (*sAh)[KPA] = (__half(*)[KPA])(dsm);
    __half (*sAl)[KPA] = (__half(*)[KPA])(dsm + 128 * KPA);
    __half (*sWh)[KP]  = (__half(*)[KP]) (dsm + 2 * 128 * KPA);
    __half (*sWl)[KP]  = (__half(*)[KP]) (dsm + 2 * 128 * KPA + 128 * KP);

    const int tid = threadIdx.x;
    const int lane = tid & 31;
    const int w = tid >> 5;
    const int rowBase = blockIdx.x * 128;

    // ---------------- Phase 1: SPMM into sAh/sAl -----------------------------
    for (int i = 0; i < 16; ++i) {
        const int rl = w * 16 + i;        // local row 0..127 (uniform per warp)
        const int r = rowBase + rl;
        float4 sacc = make_float4(0.f, 0.f, 0.f, 0.f);

        if (r < N) {
            const int e0 = rp[r];
            const int e1 = rp[r + 1];
            for (int e = e0; e < e1; e += 32) {
                const int idx = e + lane;
                const bool valid = idx < e1;
                const int   s  = valid ? src[idx] : 0;
                const float wv = valid ? ew[idx]  : 0.f;
                const int cnt = e1 - e;

                #pragma unroll
                for (int g = 0; g < 4; ++g) {
                    if (g * 8 < cnt) {
                        #pragma unroll
                        for (int j = 0; j < 8; ++j) {
                            const int   sj = __shfl_sync(0xffffffffu, s,  g * 8 + j);
                            const float wj = __shfl_sync(0xffffffffu, wv, g * 8 + j);
                            const uint2 gv = *(const uint2*)(hin + (size_t)sj * H + lane * 4);
                            const float2 f0 = __half22float2(*(const __half2*)&gv.x);
                            const float2 f1 = __half22float2(*(const __half2*)&gv.y);
                            sacc.x += wj * f0.x; sacc.y += wj * f0.y;
                            sacc.z += wj * f1.x; sacc.w += wj * f1.y;
                        }
                    }
                }
            }
        }
        // split to hi/lo fp16 and store (zeros for rows >= N)
        __half h0 = __float2half_rn(sacc.x), h1 = __float2half_rn(sacc.y);
        __half h2 = __float2half_rn(sacc.z), h3 = __float2half_rn(sacc.w);
        __half l0 = __float2half_rn(sacc.x - __half2float(h0));
        __half l1 = __float2half_rn(sacc.y - __half2float(h1));
        __half l2 = __float2half_rn(sacc.z - __half2float(h2));
        __half l3 = __float2half_rn(sacc.w - __half2float(h3));
        __half2 hp0 = __halves2half2(h0, h1), hp1 = __halves2half2(h2, h3);
        __half2 lp0 = __halves2half2(l0, l1), lp1 = __halves2half2(l2, l3);
        *(uint2*)&sAh[rl][lane * 4] = make_uint2(*(unsigned*)&hp0, *(unsigned*)&hp1);
        *(uint2*)&sAl[rl][lane * 4] = make_uint2(*(unsigned*)&lp0, *(unsigned*)&lp1);
    }
    __syncthreads();

    // ---------------- Phase 2: MMA (round-13 proven structure) ---------------
    const int rowA = w * 16 + (lane & 15);
    const int kAc  = (lane >> 4) * 8;
    const int rowW = (lane & 7) + ((lane & 16) ? 8 : 0);
    const int kWc  = ((lane >> 3) & 1) * 8;

    float acc[16][4];
    #pragma unroll
    for (int t = 0; t < 16; ++t)
        #pragma unroll
        for (int j = 0; j < 4; ++j) acc[t][j] = 0.f;

    const unsigned aHbase = s2u(&sAh[rowA][kAc]);
    const unsigned aLbase = s2u(&sAl[rowA][kAc]);

    for (int kb = 0; kb < 128; kb += 32) {
        if (kb) __syncthreads();   // protect W tile overwrite
        // W slices: WT[n][kb..kb+31]
        #pragma unroll
        for (int p = 0; p < 2; ++p) {
            int idx = p * 256 + tid;
            int n = idx >> 2, c = (idx & 3) * 8;
            *(uint4*)&sWh[n][c] = *(const uint4*)(WThi + n * 128 + kb + c);
            *(uint4*)&sWl[n][c] = *(const uint4*)(WTlo + n * 128 + kb + c);
        }
        __syncthreads();

        const unsigned aH = aHbase + kb * 2;
        const unsigned aL = aLbase + kb * 2;
        const unsigned bH = s2u(&sWh[rowW][kWc]);
        const unsigned bL = s2u(&sWl[rowW][kWc]);

        #pragma unroll
        for (int ks = 0; ks < 2; ++ks) {
            unsigned ah[4], al[4];
            LDSM_X4(ah[0], ah[1], ah[2], ah[3], aH + ks * 32);
            LDSM_X4(al[0], al[1], al[2], al[3], aL + ks * 32);
            #pragma unroll
            for (int ntp = 0; ntp < 8; ++ntp) {
                const unsigned off = (unsigned)(ntp * 16 * KP + ks * 16) * 2;
                unsigned bh0, bh1, bh2, bh3, bl0, bl1, bl2, bl3;
                LDSM_X4(bh0, bh1, bh2, bh3, bH + off);
                LDSM_X4(bl0, bl1, bl2, bl3, bL + off);
                MMA(acc[2 * ntp],     ah, bh0, bh1);   // hi*hi
                MMA(acc[2 * ntp],     ah, bl0, bl1);   // hi*lo
                MMA(acc[2 * ntp],     al, bh0, bh1);   // lo*hi
                MMA(acc[2 * ntp + 1], ah, bh2, bh3);
                MMA(acc[2 * ntp + 1], ah, bl2, bl3);
                MMA(acc[2 * ntp + 1], al, bh2, bh3);
            }
        }
    }

    const int r0 = rowBase + w * 16 + (lane >> 2);
    const int colb = (lane & 3) * 2;
    #pragma unroll
    for (int nt = 0; nt < 16; ++nt) {
        if (r0 < N) {
            __half2 h = __floats2half2_rn(tanhf(acc[nt][0]), tanhf(acc[nt][1]));
            *(__half2*)(C + (size_t)r0 * 128 + nt * 8 + colb) = h;
        }
        if (r0 + 8 < N) {
            __half2 h = __floats2half2_rn(tanhf(acc[nt][2]), tanhf(acc[nt][3]));
            *(__half2*)(C + (size_t)(r0 + 8) * 128 + nt * 8 + colb) = h;
        }
    }
}

// --------- Layer-3 SPMM (round-11 verbatim): 40 feats, tanh fused ------------
__global__ __launch_bounds__(256) void spmm_h40_tanh(const __half* __restrict__ hin,
                                                     const int* __restrict__ src,
                                                     const float* __restrict__ w,
                                                     const int* __restrict__ rp,
                                                     float* __restrict__ out, int N) {
    const int lane = threadIdx.x & 31;
    const int r = blockIdx.x * 8 + (threadIdx.x >> 5);
    if (r >= N) return;
    const int e0 = rp[r];
    const int e1 = rp[r + 1];

    float2 acc = make_float2(0.f, 0.f);

    for (int e = e0; e < e1; e += 32) {
        const int idx = e + lane;
        const bool valid = idx < e1;
        const int   s  = valid ? src[idx] : 0;
        const float wv = valid ? w[idx]   : 0.f;
        const int cnt = e1 - e;

        #pragma unroll
        for (int g = 0; g < 4; ++g) {
            if (g * 8 < cnt) {
                #pragma unroll
                for (int j = 0; j < 8; ++j) {
                    const int   sj = __shfl_sync(0xffffffffu, s,  g * 8 + j);
                    const float wj = __shfl_sync(0xffffffffu, wv, g * 8 + j);
                    if (lane < 20) {
                        const __half2 gv = *(const __half2*)(hin + (size_t)sj * TMPW + lane * 2);
                        const float2 f = __half22float2(gv);
                        acc.x += wj * f.x; acc.y += wj * f.y;
                    }
                }
            }
        }
    }

    if (lane < 20) {
        float2 o = make_float2(tanhf(acc.x), tanhf(acc.y));
        *(float2*)(out + (size_t)r * CDIM + lane * 2) = o;
    }
}

// --- tmp[N,pad64](half) = A[N,128](half, exact) @ W2 (split) via MMA ---------
// Round-11 verbatim.
__global__ __launch_bounds__(256, 2) void gemm40_mma(const __half* __restrict__ A,
                                                     __half* __restrict__ out, int N) {
    __shared__ __half sA[128][KP];
    __shared__ __half sW2h[CDIM][KP2], sW2l[CDIM][KP2];
    const int tid = threadIdx.x;
    const int lane = tid & 31;
    const int w = tid >> 5;
    const int rowBase = blockIdx.x * 128;

    // W2T full-K tiles: 40 rows x 128 halves = 16 uint4 per row
    for (int i = tid; i < CDIM * 16; i += 256) {
        int n = i >> 4, c = (i & 15) * 8;
        *(uint4*)&sW2h[n][c] = *(const uint4*)(g_W2T_hi + n * H + c);
        *(uint4*)&sW2l[n][c] = *(const uint4*)(g_W2T_lo + n * H + c);
    }

    float acc[5][4];
    #pragma unroll
    for (int t = 0; t < 5; ++t)
        #pragma unroll
        for (int j = 0; j < 4; ++j) acc[t][j] = 0.f;

    for (int kb = 0; kb < 128; kb += 32) {
        __syncthreads();
        #pragma unroll
        for (int p = 0; p < 2; ++p) {
            int idx = p * 256 + tid;
            int r = idx >> 2, c = (idx & 3) * 8;
            int gr = rowBase + r;
            uint4 v = make_uint4(0u, 0u, 0u, 0u);
            if (gr < N) v = *(const uint4*)(A + (size_t)gr * H + kb + c);
            *(uint4*)&sA[r][c] = v;
        }
        __syncthreads();

        #pragma unroll
        for (int ks = 0; ks < 2; ++ks) {
            const int koff = ks * 16 + (lane & 3) * 2;
            const int kg   = kb + koff;
            const int ra   = w * 16 + (lane >> 2);
            unsigned a[4];
            a[0] = *(const unsigned*)&sA[ra][koff];
            a[1] = *(const unsigned*)&sA[ra + 8][koff];
            a[2] = *(const unsigned*)&sA[ra][koff + 8];
            a[3] = *(const unsigned*)&sA[ra + 8][koff + 8];
            #pragma unroll
            for (int nt = 0; nt < 5; ++nt) {
                const int nb = nt * 8 + (lane >> 2);
                unsigned bh0 = *(const unsigned*)&sW2h[nb][kg];
                unsigned bh1 = *(const unsigned*)&sW2h[nb][kg + 8];
                unsigned bl0 = *(const unsigned*)&sW2l[nb][kg];
                unsigned bl1 = *(const unsigned*)&sW2l[nb][kg + 8];
                MMA(acc[nt], a, bh0, bh1);   // A exact fp16: 2 passes suffice
                MMA(acc[nt], a, bl0, bl1);
            }
        }
    }

    const int r0 = rowBase + w * 16 + (lane >> 2);
    const int colb = (lane & 3) * 2;
    #pragma unroll
    for (int nt = 0; nt < 5; ++nt) {
        if (r0 < N) {
            __half2 h = __floats2half2_rn(acc[nt][0], acc[nt][1]);
            *(__half2*)(out + (size_t)r0 * TMPW + nt * 8 + colb) = h;
        }
        if (r0 + 8 < N) {
            __half2 h = __floats2half2_rn(acc[nt][2], acc[nt][3]);
            *(__half2*)(out + (size_t)(r0 + 8) * TMPW + nt * 8 + colb) = h;
        }
    }
}

extern "C" void kernel_launch(void* const* d_in, const int* in_sizes, int n_in,
                              void* d_out, int out_size) {
    const float* x    = (const float*)d_in[0];
    const int*   esrc = (const int*)d_in[1];
    const int*   edst = (const int*)d_in[2];
    const float* ew   = (const float*)d_in[3];
    const float* W0   = (const float*)d_in[4];
    const float* W1   = (const float*)d_in[5];
    const float* W2   = (const float*)d_in[6];
    float* out = (float*)d_out;

    const int N = in_sizes[0] / H;
    const int E = in_sizes[1];

    __half *xh, *hb, *tmp; int* rp;
    __half *w0h, *w0l, *w1h, *w1l;
    cudaGetSymbolAddress((void**)&xh,  g_xh);
    cudaGetSymbolAddress((void**)&hb,  g_hb);
    cudaGetSymbolAddress((void**)&tmp, g_tmp);
    cudaGetSymbolAddress((void**)&rp,  g_rowptr);
    cudaGetSymbolAddress((void**)&w0h, g_W0T_hi);
    cudaGetSymbolAddress((void**)&w0l, g_W0T_lo);
    cudaGetSymbolAddress((void**)&w1h, g_W1T_hi);
    cudaGetSymbolAddress((void**)&w1l, g_W1T_lo);

    static bool attrSet = false;
    if (!attrSet) {
        cudaFuncSetAttribute(fused_layer,
                             cudaFuncAttributeMaxDynamicSharedMemorySize, SMEM_FUSED);
        attrSet = true;
    }

    const int gemmBlocks = (N + 127) / 128;
    const int spmmBlocks = (N + 7) / 8;

    const int n2h = N * H / 2;
    const int bF = (n2h + 255) / 256;
    const int bR = (N + 256) / 256;
    const int bW = (H * H + 255) / 256;
    const int bW2 = (H * CDIM + 255) / 256;
    prep_kernel<<<bF + bR + 2 * bW + bW2, 256>>>(x, n2h, bF, edst, E, N, bR,
                                                 W0, W1, W2, bW, xh, rp);

    // layer 1: hb = tanh(spmm(xh) @ W0)   [fused]
    fused_layer<<<gemmBlocks, 256, SMEM_FUSED>>>(xh, esrc, ew, rp, w0h, w0l, hb, N);

    // layer 2: xh = tanh(spmm(hb) @ W1)   [fused; ping-pong to avoid RAW race]
    fused_layer<<<gemmBlocks, 256, SMEM_FUSED>>>(hb, esrc, ew, rp, w1h, w1l, xh, N);

    // layer 3 (reassociated): out = tanh(spmm(xh @ W2)) -- 40-wide fp16 gather
    gemm40_mma<<<gemmBlocks, 256>>>(xh, tmp, N);
    spmm_h40_tanh<<<spmmBlocks, 256>>>(tmp, esrc, ew, rp, out, N);
}

// round 15
// speedup vs baseline: 2.1847x; 2.1847x over previous
#include <cuda_runtime.h>
#include <cuda_fp16.h>
#include <math.h>

#define H 128
#define CDIM 40
#define TMPW 64   /* padded half-row stride for layer-3 gather (128B) */
#define MAXN 100000
#define KP 40     /* padded k-stride (halves) for 32-k mma smem tiles */
#define KP2 136   /* padded k-stride (halves) for full-K W2 tile */

// scratch (device globals: allocation-free rule)
__device__ __align__(16) __half g_aggh[(size_t)MAXN * H];    // 25.6 MB (spmm out, hi)
__device__ __align__(16) __half g_aggl[(size_t)MAXN * H];    // 25.6 MB (spmm out, lo)
__device__ __align__(16) __half g_xh [(size_t)MAXN * H];     // 25.6 MB
__device__ __align__(16) __half g_hb [(size_t)MAXN * H];     // 25.6 MB
__device__ __align__(16) __half g_tmp[(size_t)MAXN * TMPW];  // 12.8 MB
__device__ int g_rowptr[MAXN + 1];
// pre-split, pre-transposed weights: WT[n][k] fp16 hi/lo halves of f32
__device__ __align__(16) __half g_W0T_hi[H * H], g_W0T_lo[H * H];
__device__ __align__(16) __half g_W1T_hi[H * H], g_W1T_lo[H * H];
__device__ __align__(16) __half g_W2T_hi[CDIM * H], g_W2T_lo[CDIM * H];

__device__ __forceinline__ unsigned s2u(const void* p) {
    return (unsigned)__cvta_generic_to_shared(p);
}

#define LDSM_X4(r0, r1, r2, r3, addr)                                        \
    asm volatile("ldmatrix.sync.aligned.m8n8.x4.shared.b16 {%0,%1,%2,%3}, [%4];" \
                 : "=r"(r0), "=r"(r1), "=r"(r2), "=r"(r3) : "r"(addr))

#define MMA(cacc, a, b0, b1)                                                 \
    asm volatile("mma.sync.aligned.m16n8k16.row.col.f32.f16.f16.f32 "        \
                 "{%0,%1,%2,%3}, {%4,%5,%6,%7}, {%8,%9}, {%0,%1,%2,%3};"     \
                 : "+f"(cacc[0]), "+f"(cacc[1]), "+f"(cacc[2]), "+f"(cacc[3])\
                 : "r"(a[0]), "r"(a[1]), "r"(a[2]), "r"(a[3]), "r"(b0), "r"(b1))

// ---------------- fused prep: f2h + rowptr + 3x weight split -----------------
__global__ void prep_kernel(const float* __restrict__ x, int n2h, int bF,
                            const int* __restrict__ dst, int E, int N, int bR,
                            const float* __restrict__ W0, const float* __restrict__ W1,
                            const float* __restrict__ W2, int bW,
                            __half* __restrict__ xh, int* __restrict__ rp) {
    const int b = blockIdx.x, t = threadIdx.x;
    if (b < bF) {                                  // f32 -> f16 convert of x
        int i = b * 256 + t;
        if (i < n2h) {
            float2 v = ((const float2*)x)[i];
            ((__half2*)xh)[i] = __floats2half2_rn(v.x, v.y);
        }
    } else if (b < bF + bR) {                      // row_ptr via lower_bound
        int i = (b - bF) * 256 + t;
        if (i <= N) {
            int lo = 0, hi = E;
            while (lo < hi) {
                int m = (lo + hi) >> 1;
                if (dst[m] < i) lo = m + 1; else hi = m;
            }
            rp[i] = lo;
        }
    } else if (b < bF + bR + 2 * bW) {             // W0 / W1 split+transpose
        int wi = b - bF - bR;
        const float* W = (wi < bW) ? W0 : W1;
        __half* Th = (wi < bW) ? g_W0T_hi : g_W1T_hi;
        __half* Tl = (wi < bW) ? g_W0T_lo : g_W1T_lo;
        int i = (wi % bW) * 256 + t;
        if (i < H * H) {
            int k = i >> 7, n = i & 127;
            float v = W[k * H + n];
            __half hi = __float2half_rn(v);
            Th[n * H + k] = hi;
            Tl[n * H + k] = __float2half_rn(v - __half2float(hi));
        }
    } else {                                       // W2 split+transpose [k<128][n<40]
        int i = (b - bF - bR - 2 * bW) * 256 + t;
        if (i < H * CDIM) {
            int k = i / CDIM, n = i % CDIM;
            float v = W2[k * CDIM + n];
            __half hi = __float2half_rn(v);
            g_W2T_hi[n * H + k] = hi;
            g_W2T_lo[n * H + k] = __float2half_rn(v - __half2float(hi));
        }
    }
}

// ---- SPMM (round-13 core) with split hi/lo fp16 output (bit-identical) ------
__global__ __launch_bounds__(256) void spmm_h128(const __half* __restrict__ hin,
                                                 const int* __restrict__ src,
                                                 const float* __restrict__ w,
                                                 const int* __restrict__ rp,
                                                 __half* __restrict__ outh,
                                                 __half* __restrict__ outl, int N) {
    const int lane = threadIdx.x & 31;
    const int r = blockIdx.x * 8 + (threadIdx.x >> 5);
    if (r >= N) return;
    const int e0 = rp[r];
    const int e1 = rp[r + 1];

    float4 acc = make_float4(0.f, 0.f, 0.f, 0.f);

    for (int e = e0; e < e1; e += 32) {
        const int idx = e + lane;
        const bool valid = idx < e1;
        const int   s  = valid ? src[idx] : 0;
        const float wv = valid ? w[idx]   : 0.f;
        const int cnt = e1 - e;

        #pragma unroll
        for (int g = 0; g < 4; ++g) {
            if (g * 8 < cnt) {
                #pragma unroll
                for (int j = 0; j < 8; ++j) {
                    const int   sj = __shfl_sync(0xffffffffu, s,  g * 8 + j);
                    const float wj = __shfl_sync(0xffffffffu, wv, g * 8 + j);
                    const uint2 gv = *(const uint2*)(hin + (size_t)sj * H + lane * 4);
                    const float2 f0 = __half22float2(*(const __half2*)&gv.x);
                    const float2 f1 = __half22float2(*(const __half2*)&gv.y);
                    acc.x += wj * f0.x; acc.y += wj * f0.y;
                    acc.z += wj * f1.x; acc.w += wj * f1.y;
                }
            }
        }
    }

    // split f32 acc -> hi/lo fp16 (exactly the split the gemm used to do)
    __half h0 = __float2half_rn(acc.x), h1 = __float2half_rn(acc.y);
    __half h2 = __float2half_rn(acc.z), h3 = __float2half_rn(acc.w);
    __half l0 = __float2half_rn(acc.x - __half2float(h0));
    __half l1 = __float2half_rn(acc.y - __half2float(h1));
    __half l2 = __float2half_rn(acc.z - __half2float(h2));
    __half l3 = __float2half_rn(acc.w - __half2float(h3));
    __half2 hp0 = __halves2half2(h0, h1), hp1 = __halves2half2(h2, h3);
    __half2 lp0 = __halves2half2(l0, l1), lp1 = __halves2half2(l2, l3);
    *(uint2*)(outh + (size_t)r * H + lane * 4) = make_uint2(*(unsigned*)&hp0, *(unsigned*)&hp1);
    *(uint2*)(outl + (size_t)r * H + lane * 4) = make_uint2(*(unsigned*)&lp0, *(unsigned*)&lp1);
}

__global__ __launch_bounds__(256) void spmm_h40_tanh(const __half* __restrict__ hin,
                                                     const int* __restrict__ src,
                                                     const float* __restrict__ w,
                                                     const int* __restrict__ rp,
                                                     float* __restrict__ out, int N) {
    const int lane = threadIdx.x & 31;
    const int r = blockIdx.x * 8 + (threadIdx.x >> 5);
    if (r >= N) return;
    const int e0 = rp[r];
    const int e1 = rp[r + 1];

    float2 acc = make_float2(0.f, 0.f);

    for (int e = e0; e < e1; e += 32) {
        const int idx = e + lane;
        const bool valid = idx < e1;
        const int   s  = valid ? src[idx] : 0;
        const float wv = valid ? w[idx]   : 0.f;
        const int cnt = e1 - e;

        #pragma unroll
        for (int g = 0; g < 4; ++g) {
            if (g * 8 < cnt) {
                #pragma unroll
                for (int j = 0; j < 8; ++j) {
                    const int   sj = __shfl_sync(0xffffffffu, s,  g * 8 + j);
                    const float wj = __shfl_sync(0xffffffffu, wv, g * 8 + j);
                    if (lane < 20) {
                        const __half2 gv = *(const __half2*)(hin + (size_t)sj * TMPW + lane * 2);
                        const float2 f = __half22float2(gv);
                        acc.x += wj * f.x; acc.y += wj * f.y;
                    }
                }
            }
        }
    }

    if (lane < 20) {
        float2 o = make_float2(tanhf(acc.x), tanhf(acc.y));
        *(float2*)(out + (size_t)r * CDIM + lane * 2) = o;
    }
}

// --- C[N,128](half) = tanh(A(split fp16) @ W) MMA+LDSM; A-staging = pure copy -
__global__ __launch_bounds__(256, 2) void gemm128_mma_tanh(const __half* __restrict__ Ah,
                                                           const __half* __restrict__ Al,
                                                           const __half* __restrict__ WThi,
                                                           const __half* __restrict__ WTlo,
                                                           __half* __restrict__ C, int N) {
    __shared__ __half sAh[128][KP], sAl[128][KP];
    __shared__ __half sWh[128][KP], sWl[128][KP];
    const int tid = threadIdx.x;
    const int lane = tid & 31;
    const int w = tid >> 5;
    const int rowBase = blockIdx.x * 128;

    const int rowA = w * 16 + (lane & 15);
    const int kAc  = (lane >> 4) * 8;
    const int rowW = (lane & 7) + ((lane & 16) ? 8 : 0);
    const int kWc  = ((lane >> 3) & 1) * 8;

    float acc[16][4];
    #pragma unroll
    for (int t = 0; t < 16; ++t)
        #pragma unroll
        for (int j = 0; j < 4; ++j) acc[t][j] = 0.f;

    for (int kb = 0; kb < 128; kb += 32) {
        __syncthreads();
        // A slice: 128 rows x 32 halves, hi+lo = 2 uint4 loads + 2 STS.128 each
        #pragma unroll
        for (int p = 0; p < 2; ++p) {
            int idx = p * 256 + tid;
            int r = idx >> 2, c = (idx & 3) * 8;
            int gr = rowBase + r;
            uint4 vh = make_uint4(0u, 0u, 0u, 0u);
            uint4 vl = make_uint4(0u, 0u, 0u, 0u);
            if (gr < N) {
                vh = *(const uint4*)(Ah + (size_t)gr * H + kb + c);
                vl = *(const uint4*)(Al + (size_t)gr * H + kb + c);
            }
            *(uint4*)&sAh[r][c] = vh;
            *(uint4*)&sAl[r][c] = vl;
        }
        // W slices: WT[n][kb..kb+31]
        #pragma unroll
        for (int p = 0; p < 2; ++p) {
            int idx = p * 256 + tid;
            int n = idx >> 2, c = (idx & 3) * 8;
            *(uint4*)&sWh[n][c] = *(const uint4*)(WThi + n * 128 + kb + c);
            *(uint4*)&sWl[n][c] = *(const uint4*)(WTlo + n * 128 + kb + c);
        }
        __syncthreads();

        const unsigned aH = s2u(&sAh[rowA][kAc]);
        const unsigned aL = s2u(&sAl[rowA][kAc]);
        const unsigned bH = s2u(&sWh[rowW][kWc]);
        const unsigned bL = s2u(&sWl[rowW][kWc]);

        #pragma unroll
        for (int ks = 0; ks < 2; ++ks) {
            unsigned ah[4], al[4];
            LDSM_X4(ah[0], ah[1], ah[2], ah[3], aH + ks * 32);
            LDSM_X4(al[0], al[1], al[2], al[3], aL + ks * 32);
            #pragma unroll
            for (int ntp = 0; ntp < 8; ++ntp) {
                const unsigned off = (unsigned)(ntp * 16 * KP + ks * 16) * 2;
                unsigned bh0, bh1, bh2, bh3, bl0, bl1, bl2, bl3;
                LDSM_X4(bh0, bh1, bh2, bh3, bH + off);
                LDSM_X4(bl0, bl1, bl2, bl3, bL + off);
                MMA(acc[2 * ntp],     ah, bh0, bh1);   // hi*hi
                MMA(acc[2 * ntp],     ah, bl0, bl1);   // hi*lo
                MMA(acc[2 * ntp],     al, bh0, bh1);   // lo*hi
                MMA(acc[2 * ntp + 1], ah, bh2, bh3);
                MMA(acc[2 * ntp + 1], ah, bl2, bl3);
                MMA(acc[2 * ntp + 1], al, bh2, bh3);
            }
        }
    }

    const int r0 = rowBase + w * 16 + (lane >> 2);
    const int colb = (lane & 3) * 2;
    #pragma unroll
    for (int nt = 0; nt < 16; ++nt) {
        if (r0 < N) {
            __half2 h = __floats2half2_rn(tanhf(acc[nt][0]), tanhf(acc[nt][1]));
            *(__half2*)(C + (size_t)r0 * 128 + nt * 8 + colb) = h;
        }
        if (r0 + 8 < N) {
            __half2 h = __floats2half2_rn(tanhf(acc[nt][2]), tanhf(acc[nt][3]));
            *(__half2*)(C + (size_t)(r0 + 8) * 128 + nt * 8 + colb) = h;
        }
    }
}

// --- tmp[N,pad64](half) = A[N,128](half, exact) @ W2 (split) via MMA ---------
// Round-11/13 verbatim.
__global__ __launch_bounds__(256, 2) void gemm40_mma(const __half* __restrict__ A,
                                                     __half* __restrict__ out, int N) {
    __shared__ __half sA[128][KP];
    __shared__ __half sW2h[CDIM][KP2], sW2l[CDIM][KP2];
    const int tid = threadIdx.x;
    const int lane = tid & 31;
    const int w = tid >> 5;
    const int rowBase = blockIdx.x * 128;

    for (int i = tid; i < CDIM * 16; i += 256) {
        int n = i >> 4, c = (i & 15) * 8;
        *(uint4*)&sW2h[n][c] = *(const uint4*)(g_W2T_hi + n * H + c);
        *(uint4*)&sW2l[n][c] = *(const uint4*)(g_W2T_lo + n * H + c);
    }

    float acc[5][4];
    #pragma unroll
    for (int t = 0; t < 5; ++t)
        #pragma unroll
        for (int j = 0; j < 4; ++j) acc[t][j] = 0.f;

    for (int kb = 0; kb < 128; kb += 32) {
        __syncthreads();
        #pragma unroll
        for (int p = 0; p < 2; ++p) {
            int idx = p * 256 + tid;
            int r = idx >> 2, c = (idx & 3) * 8;
            int gr = rowBase + r;
            uint4 v = make_uint4(0u, 0u, 0u, 0u);
            if (gr < N) v = *(const uint4*)(A + (size_t)gr * H + kb + c);
            *(uint4*)&sA[r][c] = v;
        }
        __syncthreads();

        #pragma unroll
        for (int ks = 0; ks < 2; ++ks) {
            const int koff = ks * 16 + (lane & 3) * 2;
            const int kg   = kb + koff;
            const int ra   = w * 16 + (lane >> 2);
            unsigned a[4];
            a[0] = *(const unsigned*)&sA[ra][koff];
            a[1] = *(const unsigned*)&sA[ra + 8][koff];
            a[2] = *(const unsigned*)&sA[ra][koff + 8];
            a[3] = *(const unsigned*)&sA[ra + 8][koff + 8];
            #pragma unroll
            for (int nt = 0; nt < 5; ++nt) {
                const int nb = nt * 8 + (lane >> 2);
                unsigned bh0 = *(const unsigned*)&sW2h[nb][kg];
                unsigned bh1 = *(const unsigned*)&sW2h[nb][kg + 8];
                unsigned bl0 = *(const unsigned*)&sW2l[nb][kg];
                unsigned bl1 = *(const unsigned*)&sW2l[nb][kg + 8];
                MMA(acc[nt], a, bh0, bh1);   // A exact fp16: 2 passes suffice
                MMA(acc[nt], a, bl0, bl1);
            }
        }
    }

    const int r0 = rowBase + w * 16 + (lane >> 2);
    const int colb = (lane & 3) * 2;
    #pragma unroll
    for (int nt = 0; nt < 5; ++nt) {
        if (r0 < N) {
            __half2 h = __floats2half2_rn(acc[nt][0], acc[nt][1]);
            *(__half2*)(out + (size_t)r0 * TMPW + nt * 8 + colb) = h;
        }
        if (r0 + 8 < N) {
            __half2 h = __floats2half2_rn(acc[nt][2], acc[nt][3]);
            *(__half2*)(out + (size_t)(r0 + 8) * TMPW + nt * 8 + colb) = h;
        }
    }
}

extern "C" void kernel_launch(void* const* d_in, const int* in_sizes, int n_in,
                              void* d_out, int out_size) {
    const float* x    = (const float*)d_in[0];
    const int*   esrc = (const int*)d_in[1];
    const int*   edst = (const int*)d_in[2];
    const float* ew   = (const float*)d_in[3];
    const float* W0   = (const float*)d_in[4];
    const float* W1   = (const float*)d_in[5];
    const float* W2   = (const float*)d_in[6];
    float* out = (float*)d_out;

    const int N = in_sizes[0] / H;
    const int E = in_sizes[1];

    __half *aggh, *aggl, *xh, *hb, *tmp; int* rp;
    __half *w0h, *w0l, *w1h, *w1l;
    cudaGetSymbolAddress((void**)&aggh, g_aggh);
    cudaGetSymbolAddress((void**)&aggl, g_aggl);
    cudaGetSymbolAddress((void**)&xh,  g_xh);
    cudaGetSymbolAddress((void**)&hb,  g_hb);
    cudaGetSymbolAddress((void**)&tmp, g_tmp);
    cudaGetSymbolAddress((void**)&rp,  g_rowptr);
    cudaGetSymbolAddress((void**)&w0h, g_W0T_hi);
    cudaGetSymbolAddress((void**)&w0l, g_W0T_lo);
    cudaGetSymbolAddress((void**)&w1h, g_W1T_hi);
    cudaGetSymbolAddress((void**)&w1l, g_W1T_lo);

    const int gemmBlocks = (N + 127) / 128;
    const int spmmBlocks = (N + 7) / 8;

    const int n2h = N * H / 2;
    const int bF = (n2h + 255) / 256;
    const int bR = (N + 256) / 256;
    const int bW = (H * H + 255) / 256;
    const int bW2 = (H * CDIM + 255) / 256;
    prep_kernel<<<bF + bR + 2 * bW + bW2, 256>>>(x, n2h, bF, edst, E, N, bR,
                                                 W0, W1, W2, bW, xh, rp);

    // layer 1: hb = tanh(spmm(xh) @ W0)
    spmm_h128<<<spmmBlocks, 256>>>(xh, esrc, ew, rp, aggh, aggl, N);
    gemm128_mma_tanh<<<gemmBlocks, 256>>>(aggh, aggl, w0h, w0l, hb, N);

    // layer 2: hb = tanh(spmm(hb) @ W1)  (agg buffers break the RAW hazard)
    spmm_h128<<<spmmBlocks, 256>>>(hb, esrc, ew, rp, aggh, aggl, N);
    gemm128_mma_tanh<<<gemmBlocks, 256>>>(aggh, aggl, w1h, w1l, hb, N);

    // layer 3 (reassociated): out = tanh(spmm(hb @ W2)) -- 40-wide fp16 gather
    gemm40_mma<<<gemmBlocks, 256>>>(hb, tmp, N);
    spmm_h40_tanh<<<spmmBlocks, 256>>>(tmp, esrc, ew, rp, out, N);
}

// round 17
// speedup vs baseline: 2.2748x; 1.0413x over previous
#include <cuda_runtime.h>
#include <cuda_fp16.h>
#include <math.h>

#define H 128
#define CDIM 40
#define TMPW 64   /* padded half-row stride for layer-3 gather (128B) */
#define MAXN 100000
#define KP 40     /* padded k-stride (halves) for 32-k mma smem tiles */
#define KPA 136   /* padded k-stride (halves) for full-K tiles */

// scratch (device globals: allocation-free rule)
__device__ __align__(16) float  g_aggf[(size_t)MAXN * H];    // 51.2 MB (layer-2 spmm out)
__device__ __align__(16) __half g_agg16[(size_t)MAXN * H];   // 25.6 MB (layer-1 spmm out)
__device__ __align__(16) __half g_xh [(size_t)MAXN * H];     // 25.6 MB
__device__ __align__(16) __half g_hb [(size_t)MAXN * H];     // 25.6 MB
__device__ __align__(16) __half g_tmp[(size_t)MAXN * TMPW];  // 12.8 MB
__device__ int g_rowptr[MAXN + 1];
// pre-split, pre-transposed weights: WT[n][k] fp16 hi/lo halves of f32
__device__ __align__(16) __half g_W0T_hi[H * H], g_W0T_lo[H * H];
__device__ __align__(16) __half g_W1T_hi[H * H], g_W1T_lo[H * H];
__device__ __align__(16) __half g_W2T_hi[CDIM * H], g_W2T_lo[CDIM * H];

__device__ __forceinline__ unsigned s2u(const void* p) {
    return (unsigned)__cvta_generic_to_shared(p);
}

#define LDSM_X4(r0, r1, r2, r3, addr)                                        \
    asm volatile("ldmatrix.sync.aligned.m8n8.x4.shared.b16 {%0,%1,%2,%3}, [%4];" \
                 : "=r"(r0), "=r"(r1), "=r"(r2), "=r"(r3) : "r"(addr))

#define MMA(cacc, a, b0, b1)                                                 \
    asm volatile("mma.sync.aligned.m16n8k16.row.col.f32.f16.f16.f32 "        \
                 "{%0,%1,%2,%3}, {%4,%5,%6,%7}, {%8,%9}, {%0,%1,%2,%3};"     \
                 : "+f"(cacc[0]), "+f"(cacc[1]), "+f"(cacc[2]), "+f"(cacc[3])\
                 : "r"(a[0]), "r"(a[1]), "r"(a[2]), "r"(a[3]), "r"(b0), "r"(b1))

// ---------------- fused prep: f2h + rowptr + 3x weight split -----------------
__global__ void prep_kernel(const float* __restrict__ x, int n2h, int bF,
                            const int* __restrict__ dst, int E, int N, int bR,
                            const float* __restrict__ W0, const float* __restrict__ W1,
                            const float* __restrict__ W2, int bW,
                            __half* __restrict__ xh, int* __restrict__ rp) {
    const int b = blockIdx.x, t = threadIdx.x;
    if (b < bF) {                                  // f32 -> f16 convert of x
        int i = b * 256 + t;
        if (i < n2h) {
            float2 v = ((const float2*)x)[i];
            ((__half2*)xh)[i] = __floats2half2_rn(v.x, v.y);
        }
    } else if (b < bF + bR) {                      // row_ptr via lower_bound
        int i = (b - bF) * 256 + t;
        if (i <= N) {
            int lo = 0, hi = E;
            while (lo < hi) {
                int m = (lo + hi) >> 1;
                if (dst[m] < i) lo = m + 1; else hi = m;
            }
            rp[i] = lo;
        }
    } else if (b < bF + bR + 2 * bW) {             // W0 / W1 split+transpose
        int wi = b - bF - bR;
        const float* W = (wi < bW) ? W0 : W1;
        __half* Th = (wi < bW) ? g_W0T_hi : g_W1T_hi;
        __half* Tl = (wi < bW) ? g_W0T_lo : g_W1T_lo;
        int i = (wi % bW) * 256 + t;
        if (i < H * H) {
            int k = i >> 7, n = i & 127;
            float v = W[k * H + n];
            __half hi = __float2half_rn(v);
            Th[n * H + k] = hi;
            Tl[n * H + k] = __float2half_rn(v - __half2float(hi));
        }
    } else {                                       // W2 split+transpose [k<128][n<40]
        int i = (b - bF - bR - 2 * bW) * 256 + t;
        if (i < H * CDIM) {
            int k = i / CDIM, n = i % CDIM;
            float v = W2[k * CDIM + n];
            __half hi = __float2half_rn(v);
            g_W2T_hi[n * H + k] = hi;
            g_W2T_lo[n * H + k] = __float2half_rn(v - __half2float(hi));
        }
    }
}

// ---- SPMM core (round-13 proven); f32 output variant (layer 2) --------------
__global__ __launch_bounds__(256) void spmm_h128_f(const __half* __restrict__ hin,
                                                   const int* __restrict__ src,
                                                   const float* __restrict__ w,
                                                   const int* __restrict__ rp,
                                                   float* __restrict__ out, int N) {
    const int lane = threadIdx.x & 31;
    const int r = blockIdx.x * 8 + (threadIdx.x >> 5);
    if (r >= N) return;
    const int e0 = rp[r];
    const int e1 = rp[r + 1];

    float4 acc = make_float4(0.f, 0.f, 0.f, 0.f);

    for (int e = e0; e < e1; e += 32) {
        const int idx = e + lane;
        const bool valid = idx < e1;
        const int   s  = valid ? src[idx] : 0;
        const float wv = valid ? w[idx]   : 0.f;
        const int cnt = e1 - e;

        #pragma unroll
        for (int g = 0; g < 4; ++g) {
            if (g * 8 < cnt) {
                #pragma unroll
                for (int j = 0; j < 8; ++j) {
                    const int   sj = __shfl_sync(0xffffffffu, s,  g * 8 + j);
                    const float wj = __shfl_sync(0xffffffffu, wv, g * 8 + j);
                    const uint2 gv = *(const uint2*)(hin + (size_t)sj * H + lane * 4);
                    const float2 f0 = __half22float2(*(const __half2*)&gv.x);
                    const float2 f1 = __half22float2(*(const __half2*)&gv.y);
                    acc.x += wj * f0.x; acc.y += wj * f0.y;
                    acc.z += wj * f1.x; acc.w += wj * f1.y;
                }
            }
        }
    }

    *(float4*)(out + (size_t)r * H + lane * 4) = acc;
}

// ---- SPMM core; fp16-rn output variant (layer 1; round-16 proven body) ------
__global__ __launch_bounds__(256) void spmm_h128_h(const __half* __restrict__ hin,
                                                   const int* __restrict__ src,
                                                   const float* __restrict__ w,
                                                   const int* __restrict__ rp,
                                                   __half* __restrict__ outh, int N) {
    const int lane = threadIdx.x & 31;
    const int r = blockIdx.x * 8 + (threadIdx.x >> 5);
    if (r >= N) return;
    const int e0 = rp[r];
    const int e1 = rp[r + 1];

    float4 acc = make_float4(0.f, 0.f, 0.f, 0.f);

    for (int e = e0; e < e1; e += 32) {
        const int idx = e + lane;
        const bool valid = idx < e1;
        const int   s  = valid ? src[idx] : 0;
        const float wv = valid ? w[idx]   : 0.f;
        const int cnt = e1 - e;

        #pragma unroll
        for (int g = 0; g < 4; ++g) {
            if (g * 8 < cnt) {
                #pragma unroll
                for (int j = 0; j < 8; ++j) {
                    const int   sj = __shfl_sync(0xffffffffu, s,  g * 8 + j);
                    const float wj = __shfl_sync(0xffffffffu, wv, g * 8 + j);
                    const uint2 gv = *(const uint2*)(hin + (size_t)sj * H + lane * 4);
                    const float2 f0 = __half22float2(*(const __half2*)&gv.x);
                    const float2 f1 = __half22float2(*(const __half2*)&gv.y);
                    acc.x += wj * f0.x; acc.y += wj * f0.y;
                    acc.z += wj * f1.x; acc.w += wj * f1.y;
                }
            }
        }
    }

    __half2 p0 = __floats2half2_rn(acc.x, acc.y);
    __half2 p1 = __floats2half2_rn(acc.z, acc.w);
    *(uint2*)(outh + (size_t)r * H + lane * 4) = make_uint2(*(unsigned*)&p0, *(unsigned*)&p1);
}

__global__ __launch_bounds__(256) void spmm_h40_tanh(const __half* __restrict__ hin,
                                                     const int* __restrict__ src,
                                                     const float* __restrict__ w,
                                                     const int* __restrict__ rp,
                                                     float* __restrict__ out, int N) {
    const int lane = threadIdx.x & 31;
    const int r = blockIdx.x * 8 + (threadIdx.x >> 5);
    if (r >= N) return;
    const int e0 = rp[r];
    const int e1 = rp[r + 1];

    float2 acc = make_float2(0.f, 0.f);

    for (int e = e0; e < e1; e += 32) {
        const int idx = e + lane;
        const bool valid = idx < e1;
        const int   s  = valid ? src[idx] : 0;
        const float wv = valid ? w[idx]   : 0.f;
        const int cnt = e1 - e;

        #pragma unroll
        for (int g = 0; g < 4; ++g) {
            if (g * 8 < cnt) {
                #pragma unroll
                for (int j = 0; j < 8; ++j) {
                    const int   sj = __shfl_sync(0xffffffffu, s,  g * 8 + j);
                    const float wj = __shfl_sync(0xffffffffu, wv, g * 8 + j);
                    if (lane < 20) {
                        const __half2 gv = *(const __half2*)(hin + (size_t)sj * TMPW + lane * 2);
                        const float2 f = __half22float2(gv);
                        acc.x += wj * f.x; acc.y += wj * f.y;
                    }
                }
            }
        }
    }

    if (lane < 20) {
        float2 o = make_float2(tanhf(acc.x), tanhf(acc.y));
        *(float2*)(out + (size_t)r * CDIM + lane * 2) = o;
    }
}

// --- Layer-2 GEMM: C = tanh(A(f32) @ W), 3-pass split MMA (round-13 verbatim) -
__global__ __launch_bounds__(256, 2) void gemm128_mma3_tanh(const float* __restrict__ A,
                                                            const __half* __restrict__ WThi,
                                                            const __half* __restrict__ WTlo,
                                                            __half* __restrict__ C, int N) {
    __shared__ __half sAh[128][KP], sAl[128][KP];
    __shared__ __half sWh[128][KP], sWl[128][KP];
    const int tid = threadIdx.x;
    const int lane = tid & 31;
    const int w = tid >> 5;
    const int rowBase = blockIdx.x * 128;

    const int rowA = w * 16 + (lane & 15);
    const int kAc  = (lane >> 4) * 8;
    const int rowW = (lane & 7) + ((lane & 16) ? 8 : 0);
    const int kWc  = ((lane >> 3) & 1) * 8;

    float acc[16][4];
    #pragma unroll
    for (int t = 0; t < 16; ++t)
        #pragma unroll
        for (int j = 0; j < 4; ++j) acc[t][j] = 0.f;

    for (int kb = 0; kb < 128; kb += 32) {
        __syncthreads();
        #pragma unroll
        for (int p = 0; p < 4; ++p) {
            int idx = p * 256 + tid;
            int r = idx >> 3, c = (idx & 7) * 4;
            int gr = rowBase + r;
            float4 v = make_float4(0.f, 0.f, 0.f, 0.f);
            if (gr < N) v = *(const float4*)(A + (size_t)gr * 128 + kb + c);
            __half h0 = __float2half_rn(v.x), h1 = __float2half_rn(v.y);
            __half h2 = __float2half_rn(v.z), h3 = __float2half_rn(v.w);
            __half l0 = __float2half_rn(v.x - __half2float(h0));
            __half l1 = __float2half_rn(v.y - __half2float(h1));
            __half l2 = __float2half_rn(v.z - __half2float(h2));
            __half l3 = __float2half_rn(v.w - __half2float(h3));
            *(__half2*)&sAh[r][c]     = __halves2half2(h0, h1);
            *(__half2*)&sAh[r][c + 2] = __halves2half2(h2, h3);
            *(__half2*)&sAl[r][c]     = __halves2half2(l0, l1);
            *(__half2*)&sAl[r][c + 2] = __halves2half2(l2, l3);
        }
        #pragma unroll
        for (int p = 0; p < 2; ++p) {
            int idx = p * 256 + tid;
            int n = idx >> 2, c = (idx & 3) * 8;
            *(uint4*)&sWh[n][c] = *(const uint4*)(WThi + n * 128 + kb + c);
            *(uint4*)&sWl[n][c] = *(const uint4*)(WTlo + n * 128 + kb + c);
        }
        __syncthreads();

        const unsigned aH = s2u(&sAh[rowA][kAc]);
        const unsigned aL = s2u(&sAl[rowA][kAc]);
        const unsigned bH = s2u(&sWh[rowW][kWc]);
        const unsigned bL = s2u(&sWl[rowW][kWc]);

        #pragma unroll
        for (int ks = 0; ks < 2; ++ks) {
            unsigned ah[4], al[4];
            LDSM_X4(ah[0], ah[1], ah[2], ah[3], aH + ks * 32);
            LDSM_X4(al[0], al[1], al[2], al[3], aL + ks * 32);
            #pragma unroll
            for (int ntp = 0; ntp < 8; ++ntp) {
                const unsigned off = (unsigned)(ntp * 16 * KP + ks * 16) * 2;
                unsigned bh0, bh1, bh2, bh3, bl0, bl1, bl2, bl3;
                LDSM_X4(bh0, bh1, bh2, bh3, bH + off);
                LDSM_X4(bl0, bl1, bl2, bl3, bL + off);
                MMA(acc[2 * ntp],     ah, bh0, bh1);
                MMA(acc[2 * ntp],     ah, bl0, bl1);
                MMA(acc[2 * ntp],     al, bh0, bh1);
                MMA(acc[2 * ntp + 1], ah, bh2, bh3);
                MMA(acc[2 * ntp + 1], ah, bl2, bl3);
                MMA(acc[2 * ntp + 1], al, bh2, bh3);
            }
        }
    }

    const int r0 = rowBase + w * 16 + (lane >> 2);
    const int colb = (lane & 3) * 2;
    #pragma unroll
    for (int nt = 0; nt < 16; ++nt) {
        if (r0 < N) {
            __half2 h = __floats2half2_rn(tanhf(acc[nt][0]), tanhf(acc[nt][1]));
            *(__half2*)(C + (size_t)r0 * 128 + nt * 8 + colb) = h;
        }
        if (r0 + 8 < N) {
            __half2 h = __floats2half2_rn(tanhf(acc[nt][2]), tanhf(acc[nt][3]));
            *(__half2*)(C + (size_t)(r0 + 8) * 128 + nt * 8 + colb) = h;
        }
    }
}

// --- Layer-1 GEMM: C = tanh(A(fp16) @ W(split)), 2-pass (round-16 proven body)
__global__ __launch_bounds__(256, 2) void gemm128_mma2_tanh(const __half* __restrict__ A,
                                                            const __half* __restrict__ WThi,
                                                            const __half* __restrict__ WTlo,
                                                            __half* __restrict__ C, int N) {
    __shared__ __half sA[128][KP];
    __shared__ __half sWh[128][KP], sWl[128][KP];
    const int tid = threadIdx.x;
    const int lane = tid & 31;
    const int w = tid >> 5;
    const int rowBase = blockIdx.x * 128;

    const int rowA = w * 16 + (lane & 15);
    const int kAc  = (lane >> 4) * 8;
    const int rowW = (lane & 7) + ((lane & 16) ? 8 : 0);
    const int kWc  = ((lane >> 3) & 1) * 8;

    float acc[16][4];
    #pragma unroll
    for (int t = 0; t < 16; ++t)
        #pragma unroll
        for (int j = 0; j < 4; ++j) acc[t][j] = 0.f;

    for (int kb = 0; kb < 128; kb += 32) {
        __syncthreads();
        #pragma unroll
        for (int p = 0; p < 2; ++p) {
            int idx = p * 256 + tid;
            int r = idx >> 2, c = (idx & 3) * 8;
            int gr = rowBase + r;
            uint4 v = make_uint4(0u, 0u, 0u, 0u);
            if (gr < N) v = *(const uint4*)(A + (size_t)gr * H + kb + c);
            *(uint4*)&sA[r][c] = v;
        }
        #pragma unroll
        for (int p = 0; p < 2; ++p) {
            int idx = p * 256 + tid;
            int n = idx >> 2, c = (idx & 3) * 8;
            *(uint4*)&sWh[n][c] = *(const uint4*)(WThi + n * 128 + kb + c);
            *(uint4*)&sWl[n][c] = *(const uint4*)(WTlo + n * 128 + kb + c);
        }
        __syncthreads();

        const unsigned aB = s2u(&sA[rowA][kAc]);
        const unsigned bH = s2u(&sWh[rowW][kWc]);
        const unsigned bL = s2u(&sWl[rowW][kWc]);

        #pragma unroll
        for (int ks = 0; ks < 2; ++ks) {
            unsigned ah[4];
            LDSM_X4(ah[0], ah[1], ah[2], ah[3], aB + ks * 32);
            #pragma unroll
            for (int ntp = 0; ntp < 8; ++ntp) {
                const unsigned off = (unsigned)(ntp * 16 * KP + ks * 16) * 2;
                unsigned bh0, bh1, bh2, bh3, bl0, bl1, bl2, bl3;
                LDSM_X4(bh0, bh1, bh2, bh3, bH + off);
                LDSM_X4(bl0, bl1, bl2, bl3, bL + off);
                MMA(acc[2 * ntp],     ah, bh0, bh1);
                MMA(acc[2 * ntp],     ah, bl0, bl1);
                MMA(acc[2 * ntp + 1], ah, bh2, bh3);
                MMA(acc[2 * ntp + 1], ah, bl2, bl3);
            }
        }
    }

    const int r0 = rowBase + w * 16 + (lane >> 2);
    const int colb = (lane & 3) * 2;
    #pragma unroll
    for (int nt = 0; nt < 16; ++nt) {
        if (r0 < N) {
            __half2 h = __floats2half2_rn(tanhf(acc[nt][0]), tanhf(acc[nt][1]));
            *(__half2*)(C + (size_t)r0 * 128 + nt * 8 + colb) = h;
        }
        if (r0 + 8 < N) {
            __half2 h = __floats2half2_rn(tanhf(acc[nt][2]), tanhf(acc[nt][3]));
            *(__half2*)(C + (size_t)(r0 + 8) * 128 + nt * 8 + colb) = h;
        }
    }
}

// --- tmp[N,pad64](half) = A[N,128](half) @ W2 (split); full-K A, single sync --
__global__ __launch_bounds__(256, 2) void gemm40_mma(const __half* __restrict__ A,
                                                     __half* __restrict__ out, int N) {
    __shared__ __half sA[128][KPA];
    __shared__ __half sW2h[CDIM][KPA], sW2l[CDIM][KPA];
    const int tid = threadIdx.x;
    const int lane = tid & 31;
    const int w = tid >> 5;
    const int rowBase = blockIdx.x * 128;

    // W2T full-K tiles: 40 rows x 128 halves = 16 uint4 per row
    for (int i = tid; i < CDIM * 16; i += 256) {
        int n = i >> 4, c = (i & 15) * 8;
        *(uint4*)&sW2h[n][c] = *(const uint4*)(g_W2T_hi + n * H + c);
        *(uint4*)&sW2l[n][c] = *(const uint4*)(g_W2T_lo + n * H + c);
    }
    // A full-K tile: 128 rows x 128 halves = 2048 uint4, 8 per thread
    #pragma unroll
    for (int p = 0; p < 8; ++p) {
        int idx = p * 256 + tid;
        int r = idx >> 4, c = (idx & 15) * 8;
        int gr = rowBase + r;
        uint4 v = make_uint4(0u, 0u, 0u, 0u);
        if (gr < N) v = *(const uint4*)(A + (size_t)gr * H + c);
        *(uint4*)&sA[r][c] = v;
    }
    __syncthreads();

    float acc[5][4];
    #pragma unroll
    for (int t = 0; t < 5; ++t)
        #pragma unroll
        for (int j = 0; j < 4; ++j) acc[t][j] = 0.f;

    const int ra = w * 16 + (lane >> 2);
    #pragma unroll
    for (int kb = 0; kb < 128; kb += 16) {
        const int kg = kb + (lane & 3) * 2;
        unsigned a[4];
        a[0] = *(const unsigned*)&sA[ra][kg];
        a[1] = *(const unsigned*)&sA[ra + 8][kg];
        a[2] = *(const unsigned*)&sA[ra][kg + 8];
        a[3] = *(const unsigned*)&sA[ra + 8][kg + 8];
        #pragma unroll
        for (int nt = 0; nt < 5; ++nt) {
            const int nb = nt * 8 + (lane >> 2);
            unsigned bh0 = *(const unsigned*)&sW2h[nb][kg];
            unsigned bh1 = *(const unsigned*)&sW2h[nb][kg + 8];
            unsigned bl0 = *(const unsigned*)&sW2l[nb][kg];
            unsigned bl1 = *(const unsigned*)&sW2l[nb][kg + 8];
            MMA(acc[nt], a, bh0, bh1);
            MMA(acc[nt], a, bl0, bl1);
        }
    }

    const int r0 = rowBase + w * 16 + (lane >> 2);
    const int colb = (lane & 3) * 2;
    #pragma unroll
    for (int nt = 0; nt < 5; ++nt) {
        if (r0 < N) {
            __half2 h = __floats2half2_rn(acc[nt][0], acc[nt][1]);
            *(__half2*)(out + (size_t)r0 * TMPW + nt * 8 + colb) = h;
        }
        if (r0 + 8 < N) {
            __half2 h = __floats2half2_rn(acc[nt][2], acc[nt][3]);
            *(__half2*)(out + (size_t)(r0 + 8) * TMPW + nt * 8 + colb) = h;
        }
    }
}

extern "C" void kernel_launch(void* const* d_in, const int* in_sizes, int n_in,
                              void* d_out, int out_size) {
    const float* x    = (const float*)d_in[0];
    const int*   esrc = (const int*)d_in[1];
    const int*   edst = (const int*)d_in[2];
    const float* ew   = (const float*)d_in[3];
    const float* W0   = (const float*)d_in[4];
    const float* W1   = (const float*)d_in[5];
    const float* W2   = (const float*)d_in[6];
    float* out = (float*)d_out;

    const int N = in_sizes[0] / H;
    const int E = in_sizes[1];

    float* aggf; __half *agg16, *xh, *hb, *tmp; int* rp;
    __half *w0h, *w0l, *w1h, *w1l;
    cudaGetSymbolAddress((void**)&aggf,  g_aggf);
    cudaGetSymbolAddress((void**)&agg16, g_agg16);
    cudaGetSymbolAddress((void**)&xh,  g_xh);
    cudaGetSymbolAddress((void**)&hb,  g_hb);
    cudaGetSymbolAddress((void**)&tmp, g_tmp);
    cudaGetSymbolAddress((void**)&rp,  g_rowptr);
    cudaGetSymbolAddress((void**)&w0h, g_W0T_hi);
    cudaGetSymbolAddress((void**)&w0l, g_W0T_lo);
    cudaGetSymbolAddress((void**)&w1h, g_W1T_hi);
    cudaGetSymbolAddress((void**)&w1l, g_W1T_lo);

    const int gemmBlocks = (N + 127) / 128;
    const int spmmBlocks = (N + 7) / 8;

    const int n2h = N * H / 2;
    const int bF = (n2h + 255) / 256;
    const int bR = (N + 256) / 256;
    const int bW = (H * H + 255) / 256;
    const int bW2 = (H * CDIM + 255) / 256;
    prep_kernel<<<bF + bR + 2 * bW + bW2, 256>>>(x, n2h, bF, edst, E, N, bR,
                                                 W0, W1, W2, bW, xh, rp);

    // layer 1 (fp16-A path, error budget: +2.4e-4 rel, quadrature-validated)
    spmm_h128_h<<<spmmBlocks, 256>>>(xh, esrc, ew, rp, agg16, N);
    gemm128_mma2_tanh<<<gemmBlocks, 256>>>(agg16, w0h, w0l, hb, N);

    // layer 2 (exact split-fp16 path, round-13 verbatim)
    spmm_h128_f<<<spmmBlocks, 256>>>(hb, esrc, ew, rp, aggf, N);
    gemm128_mma3_tanh<<<gemmBlocks, 256>>>(aggf, w1h, w1l, hb, N);

    // layer 3 (reassociated): out = tanh(spmm(hb @ W2)) -- 40-wide fp16 gather
    gemm40_mma<<<gemmBlocks, 256>>>(hb, tmp, N);
    spmm_h40_tanh<<<spmmBlocks, 256>>>(tmp, esrc, ew, rp, out, N);
}